// round 12
// baseline (speedup 1.0000x reference)
#include <cuda_runtime.h>
#include <cuda_bf16.h>
#include <cstdint>

#define SEQ    8192
#define D_IN   4096
#define D_OUT  4096
#define RANK   16
#define NADP   8

// ---- tile config -----------------------------------------------------------
#define BM 128
#define BN 128
#define BKB 64                       // k-bytes (int8 elems) per chunk
#define NCHUNK (D_IN / BKB)          // 64
#define KSTEPS 2                     // 2 x k32 per chunk
#define STAGES 4

#define AB_BYTES (BM * BKB)          // 8192
#define OFF_X1 0
#define OFF_X2 (AB_BYTES)
#define OFF_W1 (2 * AB_BYTES)
#define OFF_W2 (3 * AB_BYTES)
#define STAGE_BYTES (4 * AB_BYTES)   // 32768
#define MAIN_BYTES  (STAGES * STAGE_BYTES)   // 131072

// epilogue smem region (float indices), lives AFTER the pipeline stages
#define COL_STRIDE 20
#define ADP_STRIDE 2564              // 128*20 + 4 (bank-skew pad)
#define AOUT_OFF   (NADP * ADP_STRIDE)        // 20512
#define BIAS_OFF   (AOUT_OFF + BM * RANK)     // 22560
#define SCX_OFF    (BIAS_OFF + BN)            // 22688
#define SCW_OFF    (SCX_OFF + BM)             // 22816
#define TOK_OFF    (SCW_OFF + BN)             // 22944 (int region)
#define EPI_FLOATS (TOK_OFF + BM)             // 23072
#define SMEM_TOTAL (MAIN_BYTES + EPI_FLOATS * 4)   // 223360

// ---- device scratch --------------------------------------------------------
__device__ float       g_aout[SEQ * RANK];
__device__ float       g_sxf[SEQ];              // s_x / 127 per token row
__device__ float       g_swf[D_OUT];            // s_w / 127 per output col
__device__ int         g_swbits[D_OUT];         // atomicMax scratch (|w| bits)
__device__ signed char g_qx1[(size_t)SEQ * D_IN];
__device__ signed char g_qx2[(size_t)SEQ * D_IN];
__device__ signed char g_qw1[(size_t)D_OUT * D_IN];   // transposed: [N][K]
__device__ signed char g_qw2[(size_t)D_OUT * D_IN];

// ---- PTX helpers -----------------------------------------------------------
__device__ __forceinline__ uint32_t smem_u32(const void* p) {
    uint32_t a;
    asm("{ .reg .u64 t; cvta.to.shared.u64 t, %1; cvt.u32.u64 %0, t; }"
        : "=r"(a) : "l"(p));
    return a;
}
// 64B-row swizzle: 16B-chunk ^= (row>>1)&3  (conflict-free ldmatrix phases)
#define SWZ64(o) ((o) ^ (((o) >> 3) & 0x30))

#define CP16(dst, src) \
    asm volatile("cp.async.cg.shared.global [%0], [%1], 16;" \
                 :: "r"(dst), "l"(src))
#define CP_COMMIT() asm volatile("cp.async.commit_group;" ::: "memory")
#define CP_WAIT2()  asm volatile("cp.async.wait_group 2;" ::: "memory")
#define CP_WAIT1()  asm volatile("cp.async.wait_group 1;" ::: "memory")
#define CP_WAIT0()  asm volatile("cp.async.wait_group 0;" ::: "memory")

__device__ __forceinline__ void ldsm4(uint32_t* r, uint32_t addr) {
    asm volatile("ldmatrix.sync.aligned.m8n8.x4.shared.b16 {%0,%1,%2,%3}, [%4];"
                 : "=r"(r[0]), "=r"(r[1]), "=r"(r[2]), "=r"(r[3]) : "r"(addr));
}
__device__ __forceinline__ void mma_s8(int* d, const uint32_t* a,
                                       const uint32_t* b) {
    asm volatile(
        "mma.sync.aligned.m16n8k32.row.col.s32.s8.s8.s32 "
        "{%0,%1,%2,%3}, {%4,%5,%6,%7}, {%8,%9}, {%0,%1,%2,%3};"
        : "+r"(d[0]), "+r"(d[1]), "+r"(d[2]), "+r"(d[3])
        : "r"(a[0]), "r"(a[1]), "r"(a[2]), "r"(a[3]), "r"(b[0]), "r"(b[1]));
}

// ---------------------------------------------------------------------------
// Pass W1: per-output-column max |W[:,n]| via atomicMax (idempotent)
// ---------------------------------------------------------------------------
__global__ void w_max_kernel(const float* __restrict__ W)
{
    const int n  = blockIdx.x * 256 + threadIdx.x;
    const int k0 = blockIdx.y * 256;
    float m = 0.f;
#pragma unroll 8
    for (int k = 0; k < 256; ++k)
        m = fmaxf(m, fabsf(W[(size_t)(k0 + k) * D_OUT + n]));
    atomicMax(&g_swbits[n], __float_as_int(m));   // |w| >= 0: int-monotonic
}

// ---------------------------------------------------------------------------
// Pass W2: transpose + two-level int8 quantize:
//   W[k][n] -> g_qw1/g_qw2[n][k],  w*127/s = q1 + q2/254
// ---------------------------------------------------------------------------
__global__ void convert_w_kernel(const float* __restrict__ W)
{
    __shared__ float t[32][33];
    const int n0 = blockIdx.x * 32, k0 = blockIdx.y * 32;
    const int tx = threadIdx.x, ty = threadIdx.y;   // 32 x 8
#pragma unroll
    for (int i = 0; i < 32; i += 8)
        t[ty + i][tx] = W[(size_t)(k0 + ty + i) * D_OUT + n0 + tx];
    __syncthreads();
#pragma unroll
    for (int i = 0; i < 32; i += 8) {
        const int n = n0 + ty + i;
        const float s = __int_as_float(g_swbits[n]);
        const float inv = 127.f / s;
        const float v = t[tx][ty + i];              // = W[k0+tx][n]
        const float tt = v * inv;
        const int q1 = __float2int_rn(tt);
        const int q2 = __float2int_rn((tt - (float)q1) * 254.f);
        const size_t o = (size_t)n * D_IN + k0 + tx;
        g_qw1[o] = (signed char)q1;
        g_qw2[o] = (signed char)q2;
        if (blockIdx.y == 0 && tx == 0) g_swf[n] = s * (1.f / 127.f);
    }
}

// ---------------------------------------------------------------------------
// Fused: a_out = (x @ A[e]^T) * scaling  AND  x -> (q1,q2) int8 split.
// One block per token row, 128 threads; x read exactly once (held in regs).
// ---------------------------------------------------------------------------
__global__ void lora_a_convert_kernel(const float* __restrict__ x,
                                      const float* __restrict__ A,
                                      const float* __restrict__ scalings,
                                      const int*   __restrict__ tok)
{
    const int s = blockIdx.x;
    const int t = threadIdx.x;
    const int e = tok[s];
    const float* xr = x + (size_t)s * D_IN;
    const float* Ae = A + (size_t)e * RANK * D_IN;

    // load my 32 x-values, track |max|
    float4 xv[8];
    float lmax = 0.f;
#pragma unroll
    for (int it = 0; it < 8; ++it) {
        xv[it] = *(const float4*)(xr + t * 4 + it * 512);
        lmax = fmaxf(lmax, fmaxf(fmaxf(fabsf(xv[it].x), fabsf(xv[it].y)),
                                 fmaxf(fabsf(xv[it].z), fabsf(xv[it].w))));
    }
#pragma unroll
    for (int o = 16; o > 0; o >>= 1)
        lmax = fmaxf(lmax, __shfl_xor_sync(0xffffffffu, lmax, o));
    __shared__ float smax[4];
    const int warp = t >> 5, lane = t & 31;
    if (lane == 0) smax[warp] = lmax;
    __syncthreads();
    const float sx  = fmaxf(fmaxf(smax[0], smax[1]), fmaxf(smax[2], smax[3]));
    const float inv = 127.f / sx;
    if (t == 0) g_sxf[s] = sx * (1.f / 127.f);

    float acc[RANK];
#pragma unroll
    for (int r = 0; r < RANK; ++r) acc[r] = 0.f;

#pragma unroll
    for (int it = 0; it < 8; ++it) {
        const int k = t * 4 + it * 512;
        const float4 v = xv[it];

        // two-level quantize (stores hidden under the dot-product FMAs)
        const float t0 = v.x * inv, t1 = v.y * inv, t2 = v.z * inv, t3 = v.w * inv;
        const int a0 = __float2int_rn(t0), a1 = __float2int_rn(t1);
        const int a2 = __float2int_rn(t2), a3 = __float2int_rn(t3);
        const int b0 = __float2int_rn((t0 - (float)a0) * 254.f);
        const int b1 = __float2int_rn((t1 - (float)a1) * 254.f);
        const int b2 = __float2int_rn((t2 - (float)a2) * 254.f);
        const int b3 = __float2int_rn((t3 - (float)a3) * 254.f);
        const size_t o = (size_t)s * D_IN + k;
        *(char4*)(g_qx1 + o) = make_char4((signed char)a0, (signed char)a1,
                                          (signed char)a2, (signed char)a3);
        *(char4*)(g_qx2 + o) = make_char4((signed char)b0, (signed char)b1,
                                          (signed char)b2, (signed char)b3);

#pragma unroll
        for (int r = 0; r < RANK; ++r) {
            const float4 av = *(const float4*)(Ae + r * D_IN + k);
            acc[r] += v.x * av.x + v.y * av.y + v.z * av.z + v.w * av.w;
        }
    }
#pragma unroll
    for (int r = 0; r < RANK; ++r) {
#pragma unroll
        for (int o = 16; o > 0; o >>= 1)
            acc[r] += __shfl_xor_sync(0xffffffffu, acc[r], o);
    }
    __shared__ float red[4][RANK];
    if (lane == 0) {
#pragma unroll
        for (int r = 0; r < RANK; ++r) red[warp][r] = acc[r];
    }
    __syncthreads();
    if (t < RANK) {
        const float v = red[0][t] + red[1][t] + red[2][t] + red[3][t];
        g_aout[s * RANK + t] = v * scalings[s];
    }
}

// ---------------------------------------------------------------------------
// Main fused IMMA GEMM:
//   D = sx*sw*(q1q1 + (q1q2 + q2q1)/254) + bias + aout@B[e]^T
// 128x128 tile, 64B k-chunks, 256 threads (8 warps, warp tile 32x64),
// 4-stage cp.async pipeline, ONE __syncthreads per chunk.
// ---------------------------------------------------------------------------
__device__ __forceinline__ void load_stage(uint32_t st, int kc, int m0, int n0,
                                           int tid)
{
    const int k0 = kc * BKB;
#pragma unroll
    for (int i = tid; i < BM * 4; i += 256) {       // 512 row-chunks of 16B
        const int row = i >> 2, c = i & 3;
        const uint32_t sw = SWZ64((uint32_t)(row * 64 + c * 16));
        const size_t ga = (size_t)(m0 + row) * D_IN + k0 + c * 16;
        const size_t gb = (size_t)(n0 + row) * D_IN + k0 + c * 16;
        CP16(st + OFF_X1 + sw, g_qx1 + ga);
        CP16(st + OFF_X2 + sw, g_qx2 + ga);
        CP16(st + OFF_W1 + sw, g_qw1 + gb);
        CP16(st + OFF_W2 + sw, g_qw2 + gb);
    }
}

__global__ __launch_bounds__(256, 1)
void fused_mma_kernel(const float* __restrict__ bias,
                      const float* __restrict__ Bbuf,
                      const int*   __restrict__ tok,
                      float*       __restrict__ out)
{
    extern __shared__ __align__(1024) char smem[];
    const uint32_t sb = smem_u32(smem);
    const int tid  = threadIdx.x;
    const int lane = tid & 31;
    const int wid  = tid >> 5;
    const int wm   = wid >> 1;          // 0..3 -> m offset wm*32
    const int wn   = wid & 1;           // 0..1 -> n offset wn*64
    const int m0 = blockIdx.y * BM;
    const int n0 = blockIdx.x * BN;

    // swizzled lane offsets (ks=0); ks toggles bit 5 (32B) post-swizzle
    uint32_t aswz[2], bswz[4];
#pragma unroll
    for (int mt = 0; mt < 2; ++mt)
        aswz[mt] = SWZ64((uint32_t)((wm * 32 + mt * 16 + (lane & 15)) * 64
                                    + ((lane >> 4) & 1) * 16));
#pragma unroll
    for (int ntp = 0; ntp < 4; ++ntp)
        bswz[ntp] = SWZ64((uint32_t)((wn * 64 + ntp * 16 + ((lane >> 4) & 1) * 8
                                      + (lane & 7)) * 64
                                     + ((lane >> 3) & 1) * 16));

    int acc1[2][8][4], acc23[2][8][4];
#pragma unroll
    for (int mt = 0; mt < 2; ++mt)
#pragma unroll
        for (int nt = 0; nt < 8; ++nt)
#pragma unroll
            for (int q = 0; q < 4; ++q) { acc1[mt][nt][q] = 0; acc23[mt][nt][q] = 0; }

    // prologue: fill stages 0..2
    load_stage(sb + 0 * STAGE_BYTES, 0, m0, n0, tid); CP_COMMIT();
    load_stage(sb + 1 * STAGE_BYTES, 1, m0, n0, tid); CP_COMMIT();
    load_stage(sb + 2 * STAGE_BYTES, 2, m0, n0, tid); CP_COMMIT();

    // stage epilogue data into its DEDICATED region (overlapped with pipeline)
    float* ef = (float*)(smem + MAIN_BYTES);
    int* stok = (int*)(ef + TOK_OFF);
    for (int i = tid; i < NADP * BN * 4; i += 256) {      // 4096 float4s
        const int e = i >> 9, rem = i & 511, c = rem >> 2, q = rem & 3;
        const float4 v = ((const float4*)(Bbuf + ((size_t)e * D_OUT + n0 + c) * RANK))[q];
        *(float4*)(ef + e * ADP_STRIDE + c * COL_STRIDE + q * 4) = v;
    }
    for (int i = tid; i < BM * RANK / 4; i += 256)
        ((float4*)(ef + AOUT_OFF))[i] =
            ((const float4*)(g_aout + (size_t)m0 * RANK))[i];
    for (int i = tid; i < BN / 4; i += 256)
        ((float4*)(ef + BIAS_OFF))[i] = ((const float4*)(bias + n0))[i];
    for (int i = tid; i < BM / 4; i += 256)
        ((float4*)(ef + SCX_OFF))[i] = ((const float4*)(g_sxf + m0))[i];
    for (int i = tid; i < BN / 4; i += 256)
        ((float4*)(ef + SCW_OFF))[i] = ((const float4*)(g_swf + n0))[i];
    if (tid < BM) stok[tid] = tok[m0 + tid];

    for (int ci = 0; ci < NCHUNK; ++ci) {
        if (ci <= NCHUNK - 3)      { CP_WAIT2(); }
        else if (ci == NCHUNK - 2) { CP_WAIT1(); }
        else                       { CP_WAIT0(); }
        __syncthreads();   // data(ci) visible; buffer (ci-1)%4 fully consumed

        if (ci + 3 < NCHUNK) {
            load_stage(sb + (uint32_t)((ci + 3) & 3) * STAGE_BYTES,
                       ci + 3, m0, n0, tid);
            CP_COMMIT();
        }

        const uint32_t st = sb + (uint32_t)(ci & 3) * STAGE_BYTES;
#pragma unroll
        for (int ks = 0; ks < KSTEPS; ++ks) {
            const uint32_t kx = (uint32_t)ks << 5;
            uint32_t x1[2][4], x2[2][4], w1[8][2], w2[8][2];
#pragma unroll
            for (int mt = 0; mt < 2; ++mt) {
                ldsm4(x1[mt], st + OFF_X1 + (aswz[mt] ^ kx));
                ldsm4(x2[mt], st + OFF_X2 + (aswz[mt] ^ kx));
            }
#pragma unroll
            for (int ntp = 0; ntp < 4; ++ntp) {
                uint32_t t4[4];
                ldsm4(t4, st + OFF_W1 + (bswz[ntp] ^ kx));
                w1[2 * ntp][0] = t4[0]; w1[2 * ntp][1] = t4[1];
                w1[2 * ntp + 1][0] = t4[2]; w1[2 * ntp + 1][1] = t4[3];
                ldsm4(t4, st + OFF_W2 + (bswz[ntp] ^ kx));
                w2[2 * ntp][0] = t4[0]; w2[2 * ntp][1] = t4[1];
                w2[2 * ntp + 1][0] = t4[2]; w2[2 * ntp + 1][1] = t4[3];
            }
#pragma unroll
            for (int mt = 0; mt < 2; ++mt)
#pragma unroll
                for (int nt = 0; nt < 8; ++nt) {
                    mma_s8(acc1[mt][nt],  x1[mt], w1[nt]);
                    mma_s8(acc23[mt][nt], x1[mt], w2[nt]);
                    mma_s8(acc23[mt][nt], x2[mt], w1[nt]);
                }
        }
    }

    // ---- combine + store --------------------------------------------------
#pragma unroll
    for (int rr = 0; rr < 4; ++rr) {
        const int mt = rr >> 1, half = rr & 1;
        const int r = wm * 32 + mt * 16 + half * 8 + (lane >> 2);
        const int e = stok[r];
        const float scx = ef[SCX_OFF + r];
        const float* ar = ef + AOUT_OFF + r * RANK;
        const float4 a0 = *(const float4*)(ar + 0);
        const float4 a1 = *(const float4*)(ar + 4);
        const float4 a2 = *(const float4*)(ar + 8);
        const float4 a3 = *(const float4*)(ar + 12);
        const float* Be = ef + e * ADP_STRIDE;
        float* outp = out + (size_t)(m0 + r) * D_OUT + n0;
#pragma unroll
        for (int nt = 0; nt < 8; ++nt) {
            const int col0 = wn * 64 + nt * 8 + 2 * (lane & 3);
            float v2[2];
#pragma unroll
            for (int c = 0; c < 2; ++c) {
                const int col = col0 + c;
                const float* bp = Be + col * COL_STRIDE;
                const float4 b0 = *(const float4*)(bp + 0);
                const float4 b1 = *(const float4*)(bp + 4);
                const float4 b2 = *(const float4*)(bp + 8);
                const float4 b3 = *(const float4*)(bp + 12);
                const float g = (float)acc1[mt][nt][half * 2 + c]
                              + (float)acc23[mt][nt][half * 2 + c] * (1.f / 254.f);
                float d = g * (scx * ef[SCW_OFF + col]) + ef[BIAS_OFF + col];
                d += a0.x * b0.x + a0.y * b0.y + a0.z * b0.z + a0.w * b0.w;
                d += a1.x * b1.x + a1.y * b1.y + a1.z * b1.z + a1.w * b1.w;
                d += a2.x * b2.x + a2.y * b2.y + a2.z * b2.z + a2.w * b2.w;
                d += a3.x * b3.x + a3.y * b3.y + a3.z * b3.z + a3.w * b3.w;
                v2[c] = d;
            }
            *(float2*)(outp + col0) = make_float2(v2[0], v2[1]);
        }
    }
}

// ---------------------------------------------------------------------------
extern "C" void kernel_launch(void* const* d_in, const int* in_sizes, int n_in,
                              void* d_out, int out_size)
{
    const float* x    = (const float*)d_in[0];
    const float* W    = (const float*)d_in[1];
    const float* bias = (const float*)d_in[2];
    const float* A    = (const float*)d_in[3];
    const float* B    = (const float*)d_in[4];
    const float* scal = (const float*)d_in[5];
    const int*   tok  = (const int*)d_in[6];
    float* out = (float*)d_out;

    static int smem_set = 0;
    if (!smem_set) {
        cudaFuncSetAttribute(fused_mma_kernel,
                             cudaFuncAttributeMaxDynamicSharedMemorySize,
                             SMEM_TOTAL);
        smem_set = 1;
    }

    w_max_kernel<<<dim3(D_OUT / 256, D_IN / 256), 256>>>(W);
    convert_w_kernel<<<dim3(D_OUT / 32, D_IN / 32), dim3(32, 8)>>>(W);
    lora_a_convert_kernel<<<SEQ, 128>>>(x, A, scal, tok);
    fused_mma_kernel<<<dim3(D_OUT / BN, SEQ / BM), 256, SMEM_TOTAL>>>(bias, B, tok, out);
}

// round 14
// speedup vs baseline: 3.2399x; 3.2399x over previous
#include <cuda_runtime.h>
#include <cuda_bf16.h>
#include <cstdint>

#define SEQ    8192
#define D_IN   4096
#define D_OUT  4096
#define RANK   16
#define NADP   8

// ---- tile config -----------------------------------------------------------
#define BM 128
#define BN 128
#define BK 32                        // fp32/tf32 elements per k-chunk
#define NCHUNK (D_IN / BK)           // 128
#define KSTEPS 4                     // 4 x k8 per chunk
#define STAGES 4

#define CHUNK_FLOATS (BM * BK)       // 4096 floats = 16KB per matrix per chunk
#define OFF_A 0
#define OFF_B 16384
#define STAGE_BYTES 32768
#define MAIN_BYTES  (STAGES * STAGE_BYTES)   // 131072

// epilogue smem region (float indices), lives AFTER the pipeline stages
#define COL_STRIDE 20
#define ADP_STRIDE 2564              // 128*20 + 4 (bank-skew pad)
#define AOUT_OFF   (NADP * ADP_STRIDE)        // 20512
#define BIAS_OFF   (AOUT_OFF + BM * RANK)     // 22560
#define TOK_OFF    (BIAS_OFF + BN)            // 22688 (int region)
#define EPI_FLOATS (TOK_OFF + BM)             // 22816
#define SMEM_TOTAL (MAIN_BYTES + EPI_FLOATS * 4)   // 222336

// ---- device scratch --------------------------------------------------------
// Fragment-permuted tf32 operands. Layout (per 128x32 chunk tile = 4096 floats):
//   A: [blk16 b: 0..7][ks: 0..3] -> 512B blob; thread tt (0..31) holds 16B:
//      [ (r,c), (r+8,c), (r,c+4), (r+8,c+4) ]  with r=tt/4, c=tt%4
//   B: [blk8 nb: 0..15][ks: 0..3] -> 256B blob; thread tt holds 8B:
//      [ (k=tt%4, n=tt/4), (k=tt%4+4, n=tt/4) ]
__device__ float g_aout[SEQ * RANK];
__device__ float g_xt[(size_t)SEQ * D_IN];
__device__ float g_wt[(size_t)D_OUT * D_IN];

// ---- PTX helpers -----------------------------------------------------------
__device__ __forceinline__ uint32_t smem_u32(const void* p) {
    uint32_t a;
    asm("{ .reg .u64 t; cvta.to.shared.u64 t, %1; cvt.u32.u64 %0, t; }"
        : "=r"(a) : "l"(p));
    return a;
}
__device__ __forceinline__ float rna_tf32(float v) {
    uint32_t r;
    asm("cvt.rna.tf32.f32 %0, %1;" : "=r"(r) : "f"(v));
    return __uint_as_float(r);
}

#define CP16(dst, src) \
    asm volatile("cp.async.cg.shared.global [%0], [%1], 16;" \
                 :: "r"(dst), "l"(src))
#define CP_COMMIT() asm volatile("cp.async.commit_group;" ::: "memory")
#define CP_WAIT2()  asm volatile("cp.async.wait_group 2;" ::: "memory")
#define CP_WAIT1()  asm volatile("cp.async.wait_group 1;" ::: "memory")
#define CP_WAIT0()  asm volatile("cp.async.wait_group 0;" ::: "memory")

__device__ __forceinline__ void mma_tf32(float* d, const uint32_t* a,
                                         const uint32_t* b) {
    asm volatile(
        "mma.sync.aligned.m16n8k8.row.col.f32.tf32.tf32.f32 "
        "{%0,%1,%2,%3}, {%4,%5,%6,%7}, {%8,%9}, {%0,%1,%2,%3};"
        : "+f"(d[0]), "+f"(d[1]), "+f"(d[2]), "+f"(d[3])
        : "r"(a[0]), "r"(a[1]), "r"(a[2]), "r"(a[3]), "r"(b[0]), "r"(b[1]));
}

// ---------------------------------------------------------------------------
// W prepass: transpose + tf32-round + fragment-permute.
//   W[k][n] fp32 -> g_wt (B-fragment layout per [ntile][kchunk] tile)
// ---------------------------------------------------------------------------
__global__ void convert_w_kernel(const float* __restrict__ W)
{
    __shared__ float t[32][33];
    const int n0 = blockIdx.x * 32, k0 = blockIdx.y * 32;
    const int tx = threadIdx.x, ty = threadIdx.y;   // 32 x 8
#pragma unroll
    for (int i = 0; i < 32; i += 8)
        t[ty + i][tx] = W[(size_t)(k0 + ty + i) * D_OUT + n0 + tx];
    __syncthreads();

    const int kchunk = k0 >> 5;
    const int ks = tx >> 3, kc = tx & 7;
    const int slot = kc >> 2, c4 = kc & 3;
#pragma unroll
    for (int i = 0; i < 32; i += 8) {
        const int n = n0 + ty + i;
        const float v = t[tx][ty + i];              // = W[k0+tx][n]
        const int ntile = n >> 7, nl = n & 127, nb = nl >> 3, n8 = nl & 7;
        const size_t base = ((size_t)ntile * NCHUNK + kchunk) * CHUNK_FLOATS;
        g_wt[base + (nb * 4 + ks) * 64 + (n8 * 4 + c4) * 2 + slot] = rna_tf32(v);
    }
}

// ---------------------------------------------------------------------------
// Fused: a_out = (x @ A[e]^T) * scaling  AND  x -> tf32 fragment-permuted.
// One block per token row, 128 threads; x read exactly once (held in regs).
// ---------------------------------------------------------------------------
__global__ void lora_a_convert_kernel(const float* __restrict__ x,
                                      const float* __restrict__ A,
                                      const float* __restrict__ scalings,
                                      const int*   __restrict__ tok)
{
    const int s = blockIdx.x;
    const int t = threadIdx.x;
    const int e = tok[s];
    const float* xr = x + (size_t)s * D_IN;
    const float* Ae = A + (size_t)e * RANK * D_IN;

    const int mtile = s >> 7, mrow = s & 127;
    const int b = mrow >> 4, r16 = mrow & 15;
    const int r8 = r16 & 7, rhi = r16 >> 3;         // rhi: +8 row half

    float acc[RANK];
#pragma unroll
    for (int r = 0; r < RANK; ++r) acc[r] = 0.f;

#pragma unroll
    for (int it = 0; it < 8; ++it) {
        const int k = t * 4 + it * 512;
        const float4 v = *(const float4*)(xr + k);

        // fragment-permuted tf32 store (hidden under dot-product FMAs)
        const int kchunk = k >> 5;
        const int ks = (k >> 3) & 3;
        const int kc0 = k & 7;                       // 0 or 4
        // slot = 2*(kc>=4) + rhi ; tt = r8*4 + (kc&3)
        const int slot = ((kc0 >> 2) << 1) + rhi;
        float* dst = g_xt + ((size_t)mtile * NCHUNK + kchunk) * CHUNK_FLOATS
                   + (b * 4 + ks) * 128 + slot;
        dst[(r8 * 4 + 0) * 4] = rna_tf32(v.x);
        dst[(r8 * 4 + 1) * 4] = rna_tf32(v.y);
        dst[(r8 * 4 + 2) * 4] = rna_tf32(v.z);
        dst[(r8 * 4 + 3) * 4] = rna_tf32(v.w);

#pragma unroll
        for (int r = 0; r < RANK; ++r) {
            const float4 av = *(const float4*)(Ae + r * D_IN + k);
            acc[r] += v.x * av.x + v.y * av.y + v.z * av.z + v.w * av.w;
        }
    }
#pragma unroll
    for (int r = 0; r < RANK; ++r) {
#pragma unroll
        for (int o = 16; o > 0; o >>= 1)
            acc[r] += __shfl_xor_sync(0xffffffffu, acc[r], o);
    }
    __shared__ float red[4][RANK];
    const int warp = t >> 5, lane = t & 31;
    if (lane == 0) {
#pragma unroll
        for (int r = 0; r < RANK; ++r) red[warp][r] = acc[r];
    }
    __syncthreads();
    if (t < RANK) {
        const float v = red[0][t] + red[1][t] + red[2][t] + red[3][t];
        g_aout[s * RANK + t] = v * scalings[s];
    }
}

// ---------------------------------------------------------------------------
// Main fused TF32 GEMM:  out = x @ W + bias + aout@B[e]^T
// 128x128 tile, BK=32, 256 threads (8 warps, warp tile 32x64),
// 4-stage cp.async pipeline (contiguous 16KB tile copies), 1 sync per chunk.
// ---------------------------------------------------------------------------
__device__ __forceinline__ void load_stage(uint32_t st, int kc, int mtile,
                                           int ntile, int tid)
{
    const float* srcA = g_xt + ((size_t)mtile * NCHUNK + kc) * CHUNK_FLOATS;
    const float* srcB = g_wt + ((size_t)ntile * NCHUNK + kc) * CHUNK_FLOATS;
#pragma unroll
    for (int i = tid; i < 1024; i += 256) {         // 1024 x 16B per matrix
        CP16(st + OFF_A + i * 16, (const char*)(srcA + i * 4));
        CP16(st + OFF_B + i * 16, (const char*)(srcB + i * 4));
    }
}

__global__ __launch_bounds__(256, 1)
void fused_mma_kernel(const float* __restrict__ bias,
                      const float* __restrict__ Bbuf,
                      const int*   __restrict__ tok,
                      float*       __restrict__ out)
{
    extern __shared__ __align__(1024) char smem[];
    const uint32_t sb = smem_u32(smem);
    const int tid  = threadIdx.x;
    const int lane = tid & 31;
    const int wid  = tid >> 5;
    const int wm   = wid >> 1;          // 0..3 -> m offset wm*32
    const int wn   = wid & 1;           // 0..1 -> n offset wn*64
    const int mtile = blockIdx.y, ntile = blockIdx.x;
    const int m0 = mtile * BM, n0 = ntile * BN;

    // lane-relative fragment base offsets (ks advances by 512B for A, 256B for B)
    uint32_t abase[2], bbase[8];
#pragma unroll
    for (int mt = 0; mt < 2; ++mt)
        abase[mt] = OFF_A + (uint32_t)(wm * 2 + mt) * 2048 + lane * 16;
#pragma unroll
    for (int nt = 0; nt < 8; ++nt)
        bbase[nt] = OFF_B + (uint32_t)(wn * 8 + nt) * 1024 + lane * 8;

    float acc[2][8][4];
#pragma unroll
    for (int mt = 0; mt < 2; ++mt)
#pragma unroll
        for (int nt = 0; nt < 8; ++nt)
#pragma unroll
            for (int q = 0; q < 4; ++q) acc[mt][nt][q] = 0.f;

    // prologue: fill stages 0..2
    load_stage(sb + 0 * STAGE_BYTES, 0, mtile, ntile, tid); CP_COMMIT();
    load_stage(sb + 1 * STAGE_BYTES, 1, mtile, ntile, tid); CP_COMMIT();
    load_stage(sb + 2 * STAGE_BYTES, 2, mtile, ntile, tid); CP_COMMIT();

    // stage epilogue data into its DEDICATED region (overlapped with pipeline)
    float* ef = (float*)(smem + MAIN_BYTES);
    int* stok = (int*)(ef + TOK_OFF);
    for (int i = tid; i < NADP * BN * 4; i += 256) {      // 4096 float4s
        const int e = i >> 9, rem = i & 511, c = rem >> 2, q = rem & 3;
        const float4 v = ((const float4*)(Bbuf + ((size_t)e * D_OUT + n0 + c) * RANK))[q];
        *(float4*)(ef + e * ADP_STRIDE + c * COL_STRIDE + q * 4) = v;
    }
    for (int i = tid; i < BM * RANK / 4; i += 256)
        ((float4*)(ef + AOUT_OFF))[i] =
            ((const float4*)(g_aout + (size_t)m0 * RANK))[i];
    for (int i = tid; i < BN / 4; i += 256)
        ((float4*)(ef + BIAS_OFF))[i] = ((const float4*)(bias + n0))[i];
    if (tid < BM) stok[tid] = tok[m0 + tid];

    for (int ci = 0; ci < NCHUNK; ++ci) {
        if (ci <= NCHUNK - 3)      { CP_WAIT2(); }
        else if (ci == NCHUNK - 2) { CP_WAIT1(); }
        else                       { CP_WAIT0(); }
        __syncthreads();   // data(ci) visible; buffer (ci-1)%4 fully consumed

        if (ci + 3 < NCHUNK) {
            load_stage(sb + (uint32_t)((ci + 3) & 3) * STAGE_BYTES,
                       ci + 3, mtile, ntile, tid);
            CP_COMMIT();
        }

        const uint32_t st = sb + (uint32_t)(ci & 3) * STAGE_BYTES;
#pragma unroll
        for (int ks = 0; ks < KSTEPS; ++ks) {
            uint4 af[2];
            uint2 bf[8];
#pragma unroll
            for (int mt = 0; mt < 2; ++mt)
                af[mt] = *(const uint4*)(smem + (st - sb) + abase[mt] + ks * 512);
#pragma unroll
            for (int nt = 0; nt < 8; ++nt)
                bf[nt] = *(const uint2*)(smem + (st - sb) + bbase[nt] + ks * 256);
#pragma unroll
            for (int mt = 0; mt < 2; ++mt) {
                const uint32_t a[4] = {af[mt].x, af[mt].y, af[mt].z, af[mt].w};
#pragma unroll
                for (int nt = 0; nt < 8; ++nt) {
                    const uint32_t b[2] = {bf[nt].x, bf[nt].y};
                    mma_tf32(acc[mt][nt], a, b);
                }
            }
        }
    }

    // ---- combine + store --------------------------------------------------
#pragma unroll
    for (int rr = 0; rr < 4; ++rr) {
        const int mt = rr >> 1, half = rr & 1;
        const int r = wm * 32 + mt * 16 + half * 8 + (lane >> 2);
        const int e = stok[r];
        const float* ar = ef + AOUT_OFF + r * RANK;
        const float4 a0 = *(const float4*)(ar + 0);
        const float4 a1 = *(const float4*)(ar + 4);
        const float4 a2 = *(const float4*)(ar + 8);
        const float4 a3 = *(const float4*)(ar + 12);
        const float* Be = ef + e * ADP_STRIDE;
        float* outp = out + (size_t)(m0 + r) * D_OUT + n0;
#pragma unroll
        for (int nt = 0; nt < 8; ++nt) {
            const int col0 = wn * 64 + nt * 8 + 2 * (lane & 3);
            float v2[2];
#pragma unroll
            for (int c = 0; c < 2; ++c) {
                const int col = col0 + c;
                const float* bp = Be + col * COL_STRIDE;
                const float4 b0 = *(const float4*)(bp + 0);
                const float4 b1 = *(const float4*)(bp + 4);
                const float4 b2 = *(const float4*)(bp + 8);
                const float4 b3 = *(const float4*)(bp + 12);
                float d = acc[mt][nt][half * 2 + c] + ef[BIAS_OFF + col];
                d += a0.x * b0.x + a0.y * b0.y + a0.z * b0.z + a0.w * b0.w;
                d += a1.x * b1.x + a1.y * b1.y + a1.z * b1.z + a1.w * b1.w;
                d += a2.x * b2.x + a2.y * b2.y + a2.z * b2.z + a2.w * b2.w;
                d += a3.x * b3.x + a3.y * b3.y + a3.z * b3.z + a3.w * b3.w;
                v2[c] = d;
            }
            *(float2*)(outp + col0) = make_float2(v2[0], v2[1]);
        }
    }
}

// ---------------------------------------------------------------------------
extern "C" void kernel_launch(void* const* d_in, const int* in_sizes, int n_in,
                              void* d_out, int out_size)
{
    const float* x    = (const float*)d_in[0];
    const float* W    = (const float*)d_in[1];
    const float* bias = (const float*)d_in[2];
    const float* A    = (const float*)d_in[3];
    const float* B    = (const float*)d_in[4];
    const float* scal = (const float*)d_in[5];
    const int*   tok  = (const int*)d_in[6];
    float* out = (float*)d_out;

    static int smem_set = 0;
    if (!smem_set) {
        cudaFuncSetAttribute(fused_mma_kernel,
                             cudaFuncAttributeMaxDynamicSharedMemorySize,
                             SMEM_TOTAL);
        smem_set = 1;
    }

    convert_w_kernel<<<dim3(D_OUT / 32, D_IN / 32), dim3(32, 8)>>>(W);
    lora_a_convert_kernel<<<SEQ, 128>>>(x, A, scal, tok);
    fused_mma_kernel<<<dim3(D_OUT / BN, SEQ / BM), 256, SMEM_TOTAL>>>(bias, B, tok, out);
}

// round 15
// speedup vs baseline: 5.6538x; 1.7450x over previous
#include <cuda_runtime.h>
#include <cuda_fp16.h>
#include <cstdint>

#define SEQ    8192
#define D_IN   4096
#define D_OUT  4096
#define RANK   16
#define NADP   8

// ---- tile config -----------------------------------------------------------
#define BM 128
#define BN 128
#define BK 64                        // fp16 elements per k-chunk (128B rows)
#define NCHUNK (D_IN / BK)           // 64
#define KSTEPS 4                     // 4 x k16 per chunk
#define STAGES 4

#define AB_BYTES (BM * BK * 2)       // 16384
#define OFF_A 0
#define OFF_B AB_BYTES
#define STAGE_BYTES (2 * AB_BYTES)   // 32768
#define MAIN_BYTES  (STAGES * STAGE_BYTES)   // 131072

// epilogue smem region (float indices), lives AFTER the pipeline stages
#define COL_STRIDE 20
#define ADP_STRIDE 2564              // 128*20 + 4 (bank-skew pad)
#define AOUT_OFF   (NADP * ADP_STRIDE)        // 20512
#define BIAS_OFF   (AOUT_OFF + BM * RANK)     // 22560
#define TOK_OFF    (BIAS_OFF + BN)            // 22688 (int region)
#define EPI_FLOATS (TOK_OFF + BM)             // 22816
#define SMEM_TOTAL (MAIN_BYTES + EPI_FLOATS * 4)   // 222336

// ---- device scratch --------------------------------------------------------
__device__ float  g_aout[SEQ * RANK];
__device__ __half g_xh[(size_t)SEQ * D_IN];
__device__ __half g_wh[(size_t)D_OUT * D_IN];   // transposed: [N][K]

// ---- PTX helpers -----------------------------------------------------------
__device__ __forceinline__ uint32_t smem_u32(const void* p) {
    uint32_t a;
    asm("{ .reg .u64 t; cvta.to.shared.u64 t, %1; cvt.u32.u64 %0, t; }"
        : "=r"(a) : "l"(p));
    return a;
}
// 128B-row swizzle: 16B-chunk ^= (row & 7)
#define SWZ128(o) ((o) ^ (((o) >> 3) & 0x70))

#define CP16(dst, src) \
    asm volatile("cp.async.cg.shared.global [%0], [%1], 16;" \
                 :: "r"(dst), "l"(src))
#define CP_COMMIT() asm volatile("cp.async.commit_group;" ::: "memory")
#define CP_WAIT2()  asm volatile("cp.async.wait_group 2;" ::: "memory")
#define CP_WAIT1()  asm volatile("cp.async.wait_group 1;" ::: "memory")
#define CP_WAIT0()  asm volatile("cp.async.wait_group 0;" ::: "memory")

__device__ __forceinline__ void ldsm4(uint32_t* r, uint32_t addr) {
    asm volatile("ldmatrix.sync.aligned.m8n8.x4.shared.b16 {%0,%1,%2,%3}, [%4];"
                 : "=r"(r[0]), "=r"(r[1]), "=r"(r[2]), "=r"(r[3]) : "r"(addr));
}
__device__ __forceinline__ void mma_f16(float* d, const uint32_t* a,
                                        const uint32_t* b) {
    asm volatile(
        "mma.sync.aligned.m16n8k16.row.col.f32.f16.f16.f32 "
        "{%0,%1,%2,%3}, {%4,%5,%6,%7}, {%8,%9}, {%0,%1,%2,%3};"
        : "+f"(d[0]), "+f"(d[1]), "+f"(d[2]), "+f"(d[3])
        : "r"(a[0]), "r"(a[1]), "r"(a[2]), "r"(a[3]), "r"(b[0]), "r"(b[1]));
}

// ---------------------------------------------------------------------------
// W prepass: transpose + fp16 convert:  W[k][n] fp32 -> g_wh[n][k]
// ---------------------------------------------------------------------------
__global__ void convert_w_kernel(const float* __restrict__ W)
{
    __shared__ float t[32][33];
    const int n0 = blockIdx.x * 32, k0 = blockIdx.y * 32;
    const int tx = threadIdx.x, ty = threadIdx.y;   // 32 x 8
#pragma unroll
    for (int i = 0; i < 32; i += 8)
        t[ty + i][tx] = W[(size_t)(k0 + ty + i) * D_OUT + n0 + tx];
    __syncthreads();
#pragma unroll
    for (int i = 0; i < 32; i += 8) {
        const float v = t[tx][ty + i];              // = W[k0+tx][n0+ty+i]
        g_wh[(size_t)(n0 + ty + i) * D_IN + k0 + tx] = __float2half_rn(v);
    }
}

// ---------------------------------------------------------------------------
// Fused: a_out = (x @ A[e]^T) * scaling  AND  x -> fp16.
// One block per token row, 128 threads; x read exactly once.
// ---------------------------------------------------------------------------
__global__ void lora_a_convert_kernel(const float* __restrict__ x,
                                      const float* __restrict__ A,
                                      const float* __restrict__ scalings,
                                      const int*   __restrict__ tok)
{
    const int s = blockIdx.x;
    const int t = threadIdx.x;
    const int e = tok[s];
    const float* xr = x + (size_t)s * D_IN;
    const float* Ae = A + (size_t)e * RANK * D_IN;

    float acc[RANK];
#pragma unroll
    for (int r = 0; r < RANK; ++r) acc[r] = 0.f;

#pragma unroll
    for (int it = 0; it < 8; ++it) {
        const int k = t * 4 + it * 512;
        const float4 v = *(const float4*)(xr + k);

        // fp16 convert (hidden under the dot-product FMAs)
        const size_t o = (size_t)s * D_IN + k;
        *(__half2*)(g_xh + o)     = __floats2half2_rn(v.x, v.y);
        *(__half2*)(g_xh + o + 2) = __floats2half2_rn(v.z, v.w);

#pragma unroll
        for (int r = 0; r < RANK; ++r) {
            const float4 av = *(const float4*)(Ae + r * D_IN + k);
            acc[r] += v.x * av.x + v.y * av.y + v.z * av.z + v.w * av.w;
        }
    }
#pragma unroll
    for (int r = 0; r < RANK; ++r) {
#pragma unroll
        for (int o = 16; o > 0; o >>= 1)
            acc[r] += __shfl_xor_sync(0xffffffffu, acc[r], o);
    }
    __shared__ float red[4][RANK];
    const int warp = t >> 5, lane = t & 31;
    if (lane == 0) {
#pragma unroll
        for (int r = 0; r < RANK; ++r) red[warp][r] = acc[r];
    }
    __syncthreads();
    if (t < RANK) {
        const float v = red[0][t] + red[1][t] + red[2][t] + red[3][t];
        g_aout[s * RANK + t] = v * scalings[s];
    }
}

// ---------------------------------------------------------------------------
// Main fused fp16 HMMA GEMM:  out = x @ W + bias + aout@B[e]^T
// 128x128 tile, BK=64, 256 threads (8 warps, warp tile 32x64),
// 4-stage cp.async pipeline, ONE __syncthreads per chunk.
// ---------------------------------------------------------------------------
__device__ __forceinline__ void load_stage(uint32_t st, int kc, int m0, int n0,
                                           int tid)
{
    const int k0 = kc * BK;
#pragma unroll
    for (int i = tid; i < BM * 8; i += 256) {       // 1024 16B-chunks per matrix
        const int row = i >> 3, c = i & 7;
        const uint32_t sw = SWZ128((uint32_t)(row * 128 + c * 16));
        CP16(st + OFF_A + sw,
             (const char*)(g_xh + (size_t)(m0 + row) * D_IN + k0 + c * 8));
        CP16(st + OFF_B + sw,
             (const char*)(g_wh + (size_t)(n0 + row) * D_IN + k0 + c * 8));
    }
}

__global__ __launch_bounds__(256, 1)
void fused_mma_kernel(const float* __restrict__ bias,
                      const float* __restrict__ Bbuf,
                      const int*   __restrict__ tok,
                      float*       __restrict__ out)
{
    extern __shared__ __align__(1024) char smem[];
    const uint32_t sb = smem_u32(smem);
    const int tid  = threadIdx.x;
    const int lane = tid & 31;
    const int wid  = tid >> 5;
    const int wm   = wid >> 1;          // 0..3 -> m offset wm*32
    const int wn   = wid & 1;           // 0..1 -> n offset wn*64
    const int m0 = blockIdx.y * BM;
    const int n0 = blockIdx.x * BN;

    // swizzled lane offsets (ks=0); ks XORs bits 5-6 (32B steps) post-swizzle
    uint32_t aswz[2], bswz[4];
#pragma unroll
    for (int mt = 0; mt < 2; ++mt)
        aswz[mt] = SWZ128((uint32_t)((wm * 32 + mt * 16 + (lane & 15)) * 128
                                     + ((lane >> 4) & 1) * 16));
#pragma unroll
    for (int ntp = 0; ntp < 4; ++ntp)
        bswz[ntp] = SWZ128((uint32_t)((wn * 64 + ntp * 16 + ((lane >> 4) & 1) * 8
                                       + (lane & 7)) * 128
                                      + ((lane >> 3) & 1) * 16));

    float acc[2][8][4];
#pragma unroll
    for (int mt = 0; mt < 2; ++mt)
#pragma unroll
        for (int nt = 0; nt < 8; ++nt)
#pragma unroll
            for (int q = 0; q < 4; ++q) acc[mt][nt][q] = 0.f;

    // prologue: fill stages 0..2
    load_stage(sb + 0 * STAGE_BYTES, 0, m0, n0, tid); CP_COMMIT();
    load_stage(sb + 1 * STAGE_BYTES, 1, m0, n0, tid); CP_COMMIT();
    load_stage(sb + 2 * STAGE_BYTES, 2, m0, n0, tid); CP_COMMIT();

    // stage epilogue data into its DEDICATED region (overlapped with pipeline)
    float* ef = (float*)(smem + MAIN_BYTES);
    int* stok = (int*)(ef + TOK_OFF);
    for (int i = tid; i < NADP * BN * 4; i += 256) {      // 4096 float4s
        const int e = i >> 9, rem = i & 511, c = rem >> 2, q = rem & 3;
        const float4 v = ((const float4*)(Bbuf + ((size_t)e * D_OUT + n0 + c) * RANK))[q];
        *(float4*)(ef + e * ADP_STRIDE + c * COL_STRIDE + q * 4) = v;
    }
    for (int i = tid; i < BM * RANK / 4; i += 256)
        ((float4*)(ef + AOUT_OFF))[i] =
            ((const float4*)(g_aout + (size_t)m0 * RANK))[i];
    for (int i = tid; i < BN / 4; i += 256)
        ((float4*)(ef + BIAS_OFF))[i] = ((const float4*)(bias + n0))[i];
    if (tid < BM) stok[tid] = tok[m0 + tid];

    for (int ci = 0; ci < NCHUNK; ++ci) {
        if (ci <= NCHUNK - 3)      { CP_WAIT2(); }
        else if (ci == NCHUNK - 2) { CP_WAIT1(); }
        else                       { CP_WAIT0(); }
        __syncthreads();   // data(ci) visible; buffer (ci-1)%4 fully consumed

        if (ci + 3 < NCHUNK) {
            load_stage(sb + (uint32_t)((ci + 3) & 3) * STAGE_BYTES,
                       ci + 3, m0, n0, tid);
            CP_COMMIT();
        }

        const uint32_t st = sb + (uint32_t)(ci & 3) * STAGE_BYTES;
#pragma unroll
        for (int ks = 0; ks < KSTEPS; ++ks) {
            const uint32_t kx = (uint32_t)ks << 5;
            uint32_t af[2][4], bf[8][2];
#pragma unroll
            for (int mt = 0; mt < 2; ++mt)
                ldsm4(af[mt], st + OFF_A + (aswz[mt] ^ kx));
#pragma unroll
            for (int ntp = 0; ntp < 4; ++ntp) {
                uint32_t t4[4];
                ldsm4(t4, st + OFF_B + (bswz[ntp] ^ kx));
                bf[2 * ntp][0] = t4[0]; bf[2 * ntp][1] = t4[1];
                bf[2 * ntp + 1][0] = t4[2]; bf[2 * ntp + 1][1] = t4[3];
            }
#pragma unroll
            for (int mt = 0; mt < 2; ++mt)
#pragma unroll
                for (int nt = 0; nt < 8; ++nt)
                    mma_f16(acc[mt][nt], af[mt], bf[nt]);
        }
    }

    // ---- combine + store --------------------------------------------------
#pragma unroll
    for (int rr = 0; rr < 4; ++rr) {
        const int mt = rr >> 1, half = rr & 1;
        const int r = wm * 32 + mt * 16 + half * 8 + (lane >> 2);
        const int e = stok[r];
        const float* ar = ef + AOUT_OFF + r * RANK;
        const float4 a0 = *(const float4*)(ar + 0);
        const float4 a1 = *(const float4*)(ar + 4);
        const float4 a2 = *(const float4*)(ar + 8);
        const float4 a3 = *(const float4*)(ar + 12);
        const float* Be = ef + e * ADP_STRIDE;
        float* outp = out + (size_t)(m0 + r) * D_OUT + n0;
#pragma unroll
        for (int nt = 0; nt < 8; ++nt) {
            const int col0 = wn * 64 + nt * 8 + 2 * (lane & 3);
            float v2[2];
#pragma unroll
            for (int c = 0; c < 2; ++c) {
                const int col = col0 + c;
                const float* bp = Be + col * COL_STRIDE;
                const float4 b0 = *(const float4*)(bp + 0);
                const float4 b1 = *(const float4*)(bp + 4);
                const float4 b2 = *(const float4*)(bp + 8);
                const float4 b3 = *(const float4*)(bp + 12);
                float d = acc[mt][nt][half * 2 + c] + ef[BIAS_OFF + col];
                d += a0.x * b0.x + a0.y * b0.y + a0.z * b0.z + a0.w * b0.w;
                d += a1.x * b1.x + a1.y * b1.y + a1.z * b1.z + a1.w * b1.w;
                d += a2.x * b2.x + a2.y * b2.y + a2.z * b2.z + a2.w * b2.w;
                d += a3.x * b3.x + a3.y * b3.y + a3.z * b3.z + a3.w * b3.w;
                v2[c] = d;
            }
            *(float2*)(outp + col0) = make_float2(v2[0], v2[1]);
        }
    }
}

// ---------------------------------------------------------------------------
extern "C" void kernel_launch(void* const* d_in, const int* in_sizes, int n_in,
                              void* d_out, int out_size)
{
    const float* x    = (const float*)d_in[0];
    const float* W    = (const float*)d_in[1];
    const float* bias = (const float*)d_in[2];
    const float* A    = (const float*)d_in[3];
    const float* B    = (const float*)d_in[4];
    const float* scal = (const float*)d_in[5];
    const int*   tok  = (const int*)d_in[6];
    float* out = (float*)d_out;

    static int smem_set = 0;
    if (!smem_set) {
        cudaFuncSetAttribute(fused_mma_kernel,
                             cudaFuncAttributeMaxDynamicSharedMemorySize,
                             SMEM_TOTAL);
        smem_set = 1;
    }

    convert_w_kernel<<<dim3(D_OUT / 32, D_IN / 32), dim3(32, 8)>>>(W);
    lora_a_convert_kernel<<<SEQ, 128>>>(x, A, scal, tok);
    fused_mma_kernel<<<dim3(D_OUT / BN, SEQ / BM), 256, SMEM_TOTAL>>>(bias, B, tok, out);
}